// round 4
// baseline (speedup 1.0000x reference)
#include <cuda_runtime.h>
#include <cuda_bf16.h>
#include <cstdint>
#include <cstddef>

#define NN 50000
#define NE 600000
#define DD 128
#define HH 256
#define TM 128

// ============================ device scratch ================================
__device__ float g_agg[(size_t)NN * DD];
// weights transposed to [N][K] row-major, bf16 hi/lo split
__device__ __nv_bfloat16 g_mW0h[HH * HH], g_mW0l[HH * HH];  // msg W0^T: [256][256]
__device__ __nv_bfloat16 g_mW1h[DD * HH], g_mW1l[DD * HH];  // msg W1^T: [128][256]
__device__ __nv_bfloat16 g_uW0h[HH * HH], g_uW0l[HH * HH];
__device__ __nv_bfloat16 g_uW1h[DD * HH], g_uW1l[DD * HH];

// ============================ smem layout (bytes) ===========================
// A tiles: 128 rows x 264 halves (528B stride = 33x16B -> conflict-free ldsm)
// B chunk: kc=32 K-cols, 80B stride (5x16B -> ldsm hits all 32 banks once)
//          double-buffered, hi tile then lo tile per buffer
#define SM_B0   0                       // 256 floats
#define SM_B1   1024                    // 128 floats
#define SM_FR   1536                    // 128 ints
#define SM_TO   2048                    // 128 ints
#define SM_AHI  4096
#define SM_ALO  (4096 + 67584)          // 71680
#define SM_B    (71680 + 67584)         // 139264
#define BROW    80
#define BHALF   20480                   // 256 rows * 80B (hi part of one buffer)
#define BBUF    40960                   // hi+lo per buffer
#define SMEM_TOTAL (139264 + 2 * BBUF)  // 221184
#define AROW 528

// ============================ PTX helpers ===================================
__device__ __forceinline__ uint32_t smem_u32(const void* p) {
    uint32_t a;
    asm("{ .reg .u64 t; cvta.to.shared.u64 t, %1; cvt.u32.u64 %0, t; }" : "=r"(a) : "l"(p));
    return a;
}
__device__ __forceinline__ void ldsm_x4(uint32_t& r0, uint32_t& r1, uint32_t& r2,
                                        uint32_t& r3, uint32_t addr) {
    asm volatile("ldmatrix.sync.aligned.m8n8.x4.shared.b16 {%0,%1,%2,%3}, [%4];"
                 : "=r"(r0), "=r"(r1), "=r"(r2), "=r"(r3) : "r"(addr));
}
__device__ __forceinline__ void mma_bf16(float* d, const uint32_t* a,
                                         uint32_t b0, uint32_t b1) {
    asm volatile(
        "mma.sync.aligned.m16n8k16.row.col.f32.bf16.bf16.f32 "
        "{%0,%1,%2,%3},{%4,%5,%6,%7},{%8,%9},{%0,%1,%2,%3};"
        : "+f"(d[0]), "+f"(d[1]), "+f"(d[2]), "+f"(d[3])
        : "r"(a[0]), "r"(a[1]), "r"(a[2]), "r"(a[3]), "r"(b0), "r"(b1));
}
__device__ __forceinline__ uint32_t pack_bf16(float a, float b) {
    __nv_bfloat162 t = __floats2bfloat162_rn(a, b);
    return *reinterpret_cast<uint32_t*>(&t);
}
__device__ __forceinline__ void cpa16(uint32_t dst, const void* src) {
    asm volatile("cp.async.cg.shared.global [%0], [%1], 16;"
                 :: "r"(dst), "l"(src) : "memory");
}
#define CP_COMMIT() asm volatile("cp.async.commit_group;" ::: "memory")
#define CP_WAIT(n)  asm volatile("cp.async.wait_group %0;" :: "n"(n) : "memory")

// =========================== prelude kernels ================================
__global__ void zero_agg_kernel() {
    const size_t n4 = (size_t)NN * DD / 4;
    float4 z = make_float4(0.f, 0.f, 0.f, 0.f);
    for (size_t i = (size_t)blockIdx.x * blockDim.x + threadIdx.x; i < n4;
         i += (size_t)gridDim.x * blockDim.x)
        reinterpret_cast<float4*>(g_agg)[i] = z;
}

__device__ __forceinline__ void put_split(__nv_bfloat16* h, __nv_bfloat16* l,
                                          int idx, float w) {
    __nv_bfloat16 hi = __float2bfloat16(w);
    h[idx] = hi;
    l[idx] = __float2bfloat16(w - __bfloat162float(hi));
}

// W (row-major [K][N]) -> transposed [N][K] hi/lo
__global__ void conv_w_kernel(const float* __restrict__ mW0, const float* __restrict__ uW0,
                              const float* __restrict__ mW1, const float* __restrict__ uW1) {
    int i = blockIdx.x * blockDim.x + threadIdx.x;
    if (i >= 196608) return;
    if (i < 65536) {
        int k = i >> 8, n = i & 255;
        put_split(g_mW0h, g_mW0l, n * HH + k, mW0[i]);
    } else if (i < 131072) {
        int j = i - 65536, k = j >> 8, n = j & 255;
        put_split(g_uW0h, g_uW0l, n * HH + k, uW0[j]);
    } else if (i < 163840) {
        int j = i - 131072, k = j >> 7, n = j & 127;
        put_split(g_mW1h, g_mW1l, n * HH + k, mW1[j]);
    } else {
        int j = i - 163840, k = j >> 7, n = j & 127;
        put_split(g_uW1h, g_uW1l, n * HH + k, uW1[j]);
    }
}

// stage one kc=32 chunk of W^T [nrows][256] hi/lo into B buffer `buf`
__device__ __forceinline__ void stage_chunk(uint32_t sb, int tid, int chunk, int buf,
                                            const __nv_bfloat16* Wh,
                                            const __nv_bfloat16* Wl, int nrows) {
    const uint32_t base = sb + SM_B + (uint32_t)buf * BBUF;
    const int iters = nrows / 64;   // 4 for 256 rows, 2 for 128 rows
    #pragma unroll
    for (int i = 0; i < 4; ++i) {
        if (i >= iters) break;
        int idx = tid + i * 256;        // row*4 + seg
        int row = idx >> 2, seg = idx & 3;
        uint32_t d = base + (uint32_t)(row * BROW + seg * 16);
        const __nv_bfloat16* s = Wh + row * HH + chunk * 32 + seg * 8;
        cpa16(d, s);
        cpa16(d + BHALF, Wl + row * HH + chunk * 32 + seg * 8);
    }
}

// ============================ main MLP kernel ===============================
// is_edge=1: X=[feat[from]|feat[to]] -> msg MLP -> atomicAdd into g_agg[to]
// is_edge=0: X=[g_agg[n]|feat[n]]    -> upd MLP -> out = feat + h
__global__ void __launch_bounds__(256, 1) mlp_kernel(
    int is_edge, const float* __restrict__ feat,
    const int* __restrict__ from_idx, const int* __restrict__ to_idx,
    const float* __restrict__ b0, const float* __restrict__ b1,
    float* __restrict__ outp)
{
    extern __shared__ char smc[];
    const uint32_t sb = smem_u32(smc);
    const int tid  = threadIdx.x;
    const int wid  = tid >> 5;
    const int lane = tid & 31;
    const int wr   = wid & 3;    // row group: rows wr*32..+32
    const int wc   = wid >> 2;   // col group (0/1)
    const int lrow = ((lane >> 3) & 1) * 8 + (lane & 7);
    const int lcol = (lane >> 4) * 8;

    float* b0s = reinterpret_cast<float*>(smc + SM_B0);
    float* b1s = reinterpret_cast<float*>(smc + SM_B1);
    int*   sfr = reinterpret_cast<int*>(smc + SM_FR);
    int*   sto = reinterpret_cast<int*>(smc + SM_TO);

    const int tile0 = blockIdx.x * TM;
    const int total = is_edge ? NE : NN;
    const int rem   = min(TM, total - tile0);

    b0s[tid] = b0[tid];
    if (tid < 128) b1s[tid] = b1[tid];
    if (is_edge && tid < 128) {
        int e = tile0 + tid;
        sfr[tid] = (tid < rem) ? from_idx[e] : 0;
        sto[tid] = (tid < rem) ? to_idx[e] : 0;
    }
    __syncthreads();

    const __nv_bfloat16* W0h = is_edge ? g_mW0h : g_uW0h;
    const __nv_bfloat16* W0l = is_edge ? g_mW0l : g_uW0l;
    const __nv_bfloat16* W1h = is_edge ? g_mW1h : g_uW1h;
    const __nv_bfloat16* W1l = is_edge ? g_mW1l : g_uW1l;

    // prologue: stage GEMM1 chunk0 (hidden behind the gather)
    stage_chunk(sb, tid, 0, 0, W0h, W0l, 256);
    CP_COMMIT();

    // ---- gather X [128 x 256] fp32 -> bf16 hi/lo into A tiles --------------
    {
        const float4* f4 = reinterpret_cast<const float4*>(feat);
        const float4* a4 = reinterpret_cast<const float4*>(g_agg);
        #pragma unroll 8
        for (int it = 0; it < 32; ++it) {
            int ci = tid + it * 256;
            int r  = ci >> 6;
            int c4 = ci & 63;
            float4 v = make_float4(0.f, 0.f, 0.f, 0.f);
            if (is_edge) {
                int src = (c4 < 32) ? sfr[r] : sto[r];
                v = f4[(size_t)src * 32 + (c4 & 31)];
            } else {
                int node = tile0 + r;
                if (node < NN)
                    v = (c4 < 32) ? a4[(size_t)node * 32 + c4]
                                  : f4[(size_t)node * 32 + (c4 - 32)];
            }
            __nv_bfloat16 h0 = __float2bfloat16(v.x), h1 = __float2bfloat16(v.y);
            __nv_bfloat16 h2 = __float2bfloat16(v.z), h3 = __float2bfloat16(v.w);
            uint2 H, L;
            H.x = pack_bf16(v.x, v.y);
            H.y = pack_bf16(v.z, v.w);
            L.x = pack_bf16(v.x - __bfloat162float(h0), v.y - __bfloat162float(h1));
            L.y = pack_bf16(v.z - __bfloat162float(h2), v.w - __bfloat162float(h3));
            int off = r * AROW + c4 * 8;
            *reinterpret_cast<uint2*>(smc + SM_AHI + off) = H;
            *reinterpret_cast<uint2*>(smc + SM_ALO + off) = L;
        }
    }
    __syncthreads();

    // ======================= GEMM1: H = relu(X@W0+b0) =======================
    // warp tile 32 x 128, acc[2][16][4]
    float acc[2][16][4];
    #pragma unroll
    for (int m = 0; m < 2; ++m)
        #pragma unroll
        for (int n = 0; n < 16; ++n)
            #pragma unroll
            for (int q = 0; q < 4; ++q) acc[m][n][q] = 0.f;

    for (int c = 0; c < 8; ++c) {
        if (c < 7) stage_chunk(sb, tid, c + 1, (c + 1) & 1, W0h, W0l, 256);
        CP_COMMIT();
        CP_WAIT(1);
        __syncthreads();
        const uint32_t bbase = sb + SM_B + (uint32_t)(c & 1) * BBUF;
        #pragma unroll
        for (int ks = 0; ks < 2; ++ks) {
            const int kA = c * 32 + ks * 16;
            uint32_t ah[2][4], al[2][4];
            #pragma unroll
            for (int mt = 0; mt < 2; ++mt) {
                uint32_t aaddr = sb + SM_AHI +
                    (uint32_t)((wr * 32 + mt * 16 + lrow) * AROW + (kA + lcol) * 2);
                ldsm_x4(ah[mt][0], ah[mt][1], ah[mt][2], ah[mt][3], aaddr);
                ldsm_x4(al[mt][0], al[mt][1], al[mt][2], al[mt][3],
                        aaddr + (SM_ALO - SM_AHI));
            }
            #pragma unroll
            for (int np = 0; np < 8; ++np) {
                uint32_t baddr = bbase +
                    (uint32_t)((wc * 128 + np * 16 + lrow) * BROW + (ks * 16 + lcol) * 2);
                uint32_t bh0, bh1, bh2, bh3, bl0, bl1, bl2, bl3;
                ldsm_x4(bh0, bh1, bh2, bh3, baddr);
                ldsm_x4(bl0, bl1, bl2, bl3, baddr + BHALF);
                #pragma unroll
                for (int mt = 0; mt < 2; ++mt) {
                    mma_bf16(acc[mt][2 * np],     ah[mt], bh0, bh2);
                    mma_bf16(acc[mt][2 * np + 1], ah[mt], bh1, bh3);
                    mma_bf16(acc[mt][2 * np],     al[mt], bh0, bh2);
                    mma_bf16(acc[mt][2 * np + 1], al[mt], bh1, bh3);
                    mma_bf16(acc[mt][2 * np],     ah[mt], bl0, bl2);
                    mma_bf16(acc[mt][2 * np + 1], ah[mt], bl1, bl3);
                }
            }
        }
        __syncthreads();
    }

    // prologue for GEMM2 chunk0 (hidden behind epilogue1)
    stage_chunk(sb, tid, 0, 0, W1h, W1l, 128);
    CP_COMMIT();

    // ---- epilogue1: bias+relu, hi/lo split, write H back into A tiles ------
    #pragma unroll
    for (int mt = 0; mt < 2; ++mt)
        #pragma unroll
        for (int nt = 0; nt < 16; ++nt) {
            int cc = wc * 128 + nt * 8 + 2 * (lane & 3);
            int r0 = wr * 32 + mt * 16 + (lane >> 2);
            float* d = acc[mt][nt];
            float v0 = fmaxf(d[0] + b0s[cc], 0.f), v1 = fmaxf(d[1] + b0s[cc + 1], 0.f);
            float v2 = fmaxf(d[2] + b0s[cc], 0.f), v3 = fmaxf(d[3] + b0s[cc + 1], 0.f);
            __nv_bfloat16 h0 = __float2bfloat16(v0), h1 = __float2bfloat16(v1);
            __nv_bfloat16 h2 = __float2bfloat16(v2), h3 = __float2bfloat16(v3);
            int o0 = r0 * AROW + cc * 2;
            int o1 = (r0 + 8) * AROW + cc * 2;
            *reinterpret_cast<uint32_t*>(smc + SM_AHI + o0) = pack_bf16(v0, v1);
            *reinterpret_cast<uint32_t*>(smc + SM_AHI + o1) = pack_bf16(v2, v3);
            *reinterpret_cast<uint32_t*>(smc + SM_ALO + o0) =
                pack_bf16(v0 - __bfloat162float(h0), v1 - __bfloat162float(h1));
            *reinterpret_cast<uint32_t*>(smc + SM_ALO + o1) =
                pack_bf16(v2 - __bfloat162float(h2), v3 - __bfloat162float(h3));
        }

    // ======================= GEMM2: M = relu(H@W1+b1) =======================
    // warp tile 32 x 64, acc2[2][8][4]
    float ac2[2][8][4];
    #pragma unroll
    for (int m = 0; m < 2; ++m)
        #pragma unroll
        for (int n = 0; n < 8; ++n)
            #pragma unroll
            for (int q = 0; q < 4; ++q) ac2[m][n][q] = 0.f;

    for (int c = 0; c < 8; ++c) {
        if (c < 7) stage_chunk(sb, tid, c + 1, (c + 1) & 1, W1h, W1l, 128);
        CP_COMMIT();
        CP_WAIT(1);
        __syncthreads();
        const uint32_t bbase = sb + SM_B + (uint32_t)(c & 1) * BBUF;
        #pragma unroll
        for (int ks = 0; ks < 2; ++ks) {
            const int kA = c * 32 + ks * 16;
            uint32_t ah[2][4], al[2][4];
            #pragma unroll
            for (int mt = 0; mt < 2; ++mt) {
                uint32_t aaddr = sb + SM_AHI +
                    (uint32_t)((wr * 32 + mt * 16 + lrow) * AROW + (kA + lcol) * 2);
                ldsm_x4(ah[mt][0], ah[mt][1], ah[mt][2], ah[mt][3], aaddr);
                ldsm_x4(al[mt][0], al[mt][1], al[mt][2], al[mt][3],
                        aaddr + (SM_ALO - SM_AHI));
            }
            #pragma unroll
            for (int np = 0; np < 4; ++np) {
                uint32_t baddr = bbase +
                    (uint32_t)((wc * 64 + np * 16 + lrow) * BROW + (ks * 16 + lcol) * 2);
                uint32_t bh0, bh1, bh2, bh3, bl0, bl1, bl2, bl3;
                ldsm_x4(bh0, bh1, bh2, bh3, baddr);
                ldsm_x4(bl0, bl1, bl2, bl3, baddr + BHALF);
                #pragma unroll
                for (int mt = 0; mt < 2; ++mt) {
                    mma_bf16(ac2[mt][2 * np],     ah[mt], bh0, bh2);
                    mma_bf16(ac2[mt][2 * np + 1], ah[mt], bh1, bh3);
                    mma_bf16(ac2[mt][2 * np],     al[mt], bh0, bh2);
                    mma_bf16(ac2[mt][2 * np + 1], al[mt], bh1, bh3);
                    mma_bf16(ac2[mt][2 * np],     ah[mt], bl0, bl2);
                    mma_bf16(ac2[mt][2 * np + 1], ah[mt], bl1, bl3);
                }
            }
        }
        __syncthreads();
    }

    // ---- epilogue2: bias+relu, scatter-atomic / residual store -------------
    #pragma unroll
    for (int mt = 0; mt < 2; ++mt)
        #pragma unroll
        for (int nt = 0; nt < 8; ++nt) {
            int cc = wc * 64 + nt * 8 + 2 * (lane & 3);
            int r0 = wr * 32 + mt * 16 + (lane >> 2);
            int r1 = r0 + 8;
            float* d = ac2[mt][nt];
            float v0 = fmaxf(d[0] + b1s[cc], 0.f), v1 = fmaxf(d[1] + b1s[cc + 1], 0.f);
            float v2 = fmaxf(d[2] + b1s[cc], 0.f), v3 = fmaxf(d[3] + b1s[cc + 1], 0.f);
            if (is_edge) {
                if (r0 < rem) {
                    float* a = g_agg + (size_t)sto[r0] * DD + cc;
                    atomicAdd(a, v0);
                    atomicAdd(a + 1, v1);
                }
                if (r1 < rem) {
                    float* a = g_agg + (size_t)sto[r1] * DD + cc;
                    atomicAdd(a, v2);
                    atomicAdd(a + 1, v3);
                }
            } else {
                int n0 = tile0 + r0, n1 = tile0 + r1;
                if (n0 < NN) {
                    float2 f = *reinterpret_cast<const float2*>(feat + (size_t)n0 * DD + cc);
                    *reinterpret_cast<float2*>(outp + (size_t)n0 * DD + cc) =
                        make_float2(f.x + v0, f.y + v1);
                }
                if (n1 < NN) {
                    float2 f = *reinterpret_cast<const float2*>(feat + (size_t)n1 * DD + cc);
                    *reinterpret_cast<float2*>(outp + (size_t)n1 * DD + cc) =
                        make_float2(f.x + v2, f.y + v3);
                }
            }
        }
}

// ============================== host launch =================================
extern "C" void kernel_launch(void* const* d_in, const int* in_sizes, int n_in,
                              void* d_out, int out_size)
{
    const float* feat  = (const float*)d_in[0];
    const int*   f_idx = (const int*)  d_in[1];
    const int*   t_idx = (const int*)  d_in[2];
    const float* msgW0 = (const float*)d_in[3];
    const float* msgb0 = (const float*)d_in[4];
    const float* msgW1 = (const float*)d_in[5];
    const float* msgb1 = (const float*)d_in[6];
    const float* updW0 = (const float*)d_in[7];
    const float* updb0 = (const float*)d_in[8];
    const float* updW1 = (const float*)d_in[9];
    const float* updb1 = (const float*)d_in[10];
    float* out = (float*)d_out;

    cudaFuncSetAttribute(mlp_kernel, cudaFuncAttributeMaxDynamicSharedMemorySize, SMEM_TOTAL);

    conv_w_kernel<<<768, 256>>>(msgW0, updW0, msgW1, updW1);
    zero_agg_kernel<<<1024, 256>>>();

    const int edge_tiles = (NE + TM - 1) / TM;  // 4688
    const int node_tiles = (NN + TM - 1) / TM;  // 391
    mlp_kernel<<<edge_tiles, 256, SMEM_TOTAL>>>(1, feat, f_idx, t_idx, msgb0, msgb1, nullptr);
    mlp_kernel<<<node_tiles, 256, SMEM_TOTAL>>>(0, feat, f_idx, t_idx, updb0, updb1, out);
}

// round 5
// speedup vs baseline: 1.1004x; 1.1004x over previous
#include <cuda_runtime.h>
#include <cuda_bf16.h>
#include <cstdint>
#include <cstddef>

#define NN 50000
#define NE 600000
#define DD 128
#define HH 256
#define TM 128

// ============================ device scratch ================================
__device__ float g_agg[(size_t)NN * DD];
// weights transposed to [N][K] row-major, bf16 hi/lo split
__device__ __nv_bfloat16 g_mW0h[HH * HH], g_mW0l[HH * HH];  // msg W0^T: [256][256]
__device__ __nv_bfloat16 g_mW1h[DD * HH], g_mW1l[DD * HH];  // msg W1^T: [128][256]
__device__ __nv_bfloat16 g_uW0h[HH * HH], g_uW0l[HH * HH];
__device__ __nv_bfloat16 g_uW1h[DD * HH], g_uW1l[DD * HH];

// ============================ smem layout (bytes) ===========================
// A tiles: 128 rows x 264 halves (528B stride = 33x16B -> conflict-free ldsm)
// B chunk: kc=32 K-cols, 80B stride (5x16B -> ldsm hits all 32 banks once)
//          double-buffered, hi tile then lo tile per buffer
#define SM_B0   0                       // 256 floats
#define SM_B1   1024                    // 128 floats
#define SM_FR   1536                    // 128 ints
#define SM_TO   2048                    // 128 ints
#define SM_AHI  4096
#define SM_ALO  (4096 + 67584)          // 71680
#define SM_B    (71680 + 67584)         // 139264
#define BROW    80
#define BHALF   20480                   // 256 rows * 80B (hi part of one buffer)
#define BBUF    40960                   // hi+lo per buffer
#define SMEM_TOTAL (139264 + 2 * BBUF)  // 221184
#define AROW 528

// ============================ PTX helpers ===================================
__device__ __forceinline__ uint32_t smem_u32(const void* p) {
    uint32_t a;
    asm("{ .reg .u64 t; cvta.to.shared.u64 t, %1; cvt.u32.u64 %0, t; }" : "=r"(a) : "l"(p));
    return a;
}
__device__ __forceinline__ void ldsm_x4(uint32_t& r0, uint32_t& r1, uint32_t& r2,
                                        uint32_t& r3, uint32_t addr) {
    asm volatile("ldmatrix.sync.aligned.m8n8.x4.shared.b16 {%0,%1,%2,%3}, [%4];"
                 : "=r"(r0), "=r"(r1), "=r"(r2), "=r"(r3) : "r"(addr));
}
__device__ __forceinline__ void mma_bf16(float* d, const uint32_t* a,
                                         uint32_t b0, uint32_t b1) {
    asm volatile(
        "mma.sync.aligned.m16n8k16.row.col.f32.bf16.bf16.f32 "
        "{%0,%1,%2,%3},{%4,%5,%6,%7},{%8,%9},{%0,%1,%2,%3};"
        : "+f"(d[0]), "+f"(d[1]), "+f"(d[2]), "+f"(d[3])
        : "r"(a[0]), "r"(a[1]), "r"(a[2]), "r"(a[3]), "r"(b0), "r"(b1));
}
__device__ __forceinline__ uint32_t pack_bf16(float a, float b) {
    __nv_bfloat162 t = __floats2bfloat162_rn(a, b);
    return *reinterpret_cast<uint32_t*>(&t);
}
__device__ __forceinline__ void cpa16(uint32_t dst, const void* src) {
    asm volatile("cp.async.cg.shared.global [%0], [%1], 16;"
                 :: "r"(dst), "l"(src) : "memory");
}
#define CP_COMMIT() asm volatile("cp.async.commit_group;" ::: "memory")
#define CP_WAIT(n)  asm volatile("cp.async.wait_group %0;" :: "n"(n) : "memory")

// =========================== prelude kernels ================================
__global__ void zero_agg_kernel() {
    const size_t n4 = (size_t)NN * DD / 4;
    float4 z = make_float4(0.f, 0.f, 0.f, 0.f);
    for (size_t i = (size_t)blockIdx.x * blockDim.x + threadIdx.x; i < n4;
         i += (size_t)gridDim.x * blockDim.x)
        reinterpret_cast<float4*>(g_agg)[i] = z;
}

__device__ __forceinline__ void put_split(__nv_bfloat16* h, __nv_bfloat16* l,
                                          int idx, float w) {
    __nv_bfloat16 hi = __float2bfloat16(w);
    h[idx] = hi;
    l[idx] = __float2bfloat16(w - __bfloat162float(hi));
}

// W (row-major [K][N]) -> transposed [N][K] hi/lo
__global__ void conv_w_kernel(const float* __restrict__ mW0, const float* __restrict__ uW0,
                              const float* __restrict__ mW1, const float* __restrict__ uW1) {
    int i = blockIdx.x * blockDim.x + threadIdx.x;
    if (i >= 196608) return;
    if (i < 65536) {
        int k = i >> 8, n = i & 255;
        put_split(g_mW0h, g_mW0l, n * HH + k, mW0[i]);
    } else if (i < 131072) {
        int j = i - 65536, k = j >> 8, n = j & 255;
        put_split(g_uW0h, g_uW0l, n * HH + k, uW0[j]);
    } else if (i < 163840) {
        int j = i - 131072, k = j >> 7, n = j & 127;
        put_split(g_mW1h, g_mW1l, n * HH + k, mW1[j]);
    } else {
        int j = i - 163840, k = j >> 7, n = j & 127;
        put_split(g_uW1h, g_uW1l, n * HH + k, uW1[j]);
    }
}

// stage one kc=32 chunk of W^T [nrows][256] hi/lo into B buffer `buf` (512 thr)
__device__ __forceinline__ void stage_chunk(uint32_t sb, int tid, int chunk, int buf,
                                            const __nv_bfloat16* Wh,
                                            const __nv_bfloat16* Wl, int nrows) {
    const uint32_t base = sb + SM_B + (uint32_t)buf * BBUF;
    const int iters = nrows / 128;  // 2 for 256 rows, 1 for 128 rows
    #pragma unroll
    for (int i = 0; i < 2; ++i) {
        if (i >= iters) break;
        int idx = tid + i * 512;        // row*4 + seg
        int row = idx >> 2, seg = idx & 3;
        uint32_t d = base + (uint32_t)(row * BROW + seg * 16);
        cpa16(d, Wh + row * HH + chunk * 32 + seg * 8);
        cpa16(d + BHALF, Wl + row * HH + chunk * 32 + seg * 8);
    }
}

// ============================ main MLP kernel ===============================
// is_edge=1: X=[feat[from]|feat[to]] -> msg MLP -> atomicAdd into g_agg[to]
// is_edge=0: X=[g_agg[n]|feat[n]]    -> upd MLP -> out = feat + h
__global__ void __launch_bounds__(512, 1) mlp_kernel(
    int is_edge, const float* __restrict__ feat,
    const int* __restrict__ from_idx, const int* __restrict__ to_idx,
    const float* __restrict__ b0, const float* __restrict__ b1,
    float* __restrict__ outp)
{
    extern __shared__ char smc[];
    const uint32_t sb = smem_u32(smc);
    const int tid  = threadIdx.x;
    const int wid  = tid >> 5;
    const int lane = tid & 31;
    const int wr   = wid & 3;    // row group: rows wr*32..+32
    const int wc   = wid >> 2;   // col group (0..3)
    const int lrow = ((lane >> 3) & 1) * 8 + (lane & 7);
    const int lcol = (lane >> 4) * 8;

    float* b0s = reinterpret_cast<float*>(smc + SM_B0);
    float* b1s = reinterpret_cast<float*>(smc + SM_B1);
    int*   sfr = reinterpret_cast<int*>(smc + SM_FR);
    int*   sto = reinterpret_cast<int*>(smc + SM_TO);

    const int tile0 = blockIdx.x * TM;
    const int total = is_edge ? NE : NN;
    const int rem   = min(TM, total - tile0);

    if (tid < 256) b0s[tid] = b0[tid];
    if (tid < 128) b1s[tid] = b1[tid];
    if (is_edge && tid < 128) {
        int e = tile0 + tid;
        sfr[tid] = (tid < rem) ? from_idx[e] : 0;
        sto[tid] = (tid < rem) ? to_idx[e] : 0;
    }
    __syncthreads();

    const __nv_bfloat16* W0h = is_edge ? g_mW0h : g_uW0h;
    const __nv_bfloat16* W0l = is_edge ? g_mW0l : g_uW0l;
    const __nv_bfloat16* W1h = is_edge ? g_mW1h : g_uW1h;
    const __nv_bfloat16* W1l = is_edge ? g_mW1l : g_uW1l;

    // prologue: stage GEMM1 chunk0 (hidden behind the gather)
    stage_chunk(sb, tid, 0, 0, W0h, W0l, 256);
    CP_COMMIT();

    // ---- gather X [128 x 256] fp32 -> bf16 hi/lo into A tiles --------------
    {
        const float4* f4 = reinterpret_cast<const float4*>(feat);
        const float4* a4 = reinterpret_cast<const float4*>(g_agg);
        #pragma unroll
        for (int it = 0; it < 16; ++it) {
            int ci = tid + it * 512;
            int r  = ci >> 6;
            int c4 = ci & 63;
            float4 v = make_float4(0.f, 0.f, 0.f, 0.f);
            if (is_edge) {
                int src = (c4 < 32) ? sfr[r] : sto[r];
                v = f4[(size_t)src * 32 + (c4 & 31)];
            } else {
                int node = tile0 + r;
                if (node < NN)
                    v = (c4 < 32) ? a4[(size_t)node * 32 + c4]
                                  : f4[(size_t)node * 32 + (c4 - 32)];
            }
            __nv_bfloat16 h0 = __float2bfloat16(v.x), h1 = __float2bfloat16(v.y);
            __nv_bfloat16 h2 = __float2bfloat16(v.z), h3 = __float2bfloat16(v.w);
            uint2 H, L;
            H.x = pack_bf16(v.x, v.y);
            H.y = pack_bf16(v.z, v.w);
            L.x = pack_bf16(v.x - __bfloat162float(h0), v.y - __bfloat162float(h1));
            L.y = pack_bf16(v.z - __bfloat162float(h2), v.w - __bfloat162float(h3));
            int off = r * AROW + c4 * 8;
            *reinterpret_cast<uint2*>(smc + SM_AHI + off) = H;
            *reinterpret_cast<uint2*>(smc + SM_ALO + off) = L;
        }
    }
    __syncthreads();

    // ======================= GEMM1: H = relu(X@W0+b0) =======================
    // warp tile 32 x 64, acc[2][8][4]
    float acc[2][8][4];
    #pragma unroll
    for (int m = 0; m < 2; ++m)
        #pragma unroll
        for (int n = 0; n < 8; ++n)
            #pragma unroll
            for (int q = 0; q < 4; ++q) acc[m][n][q] = 0.f;

    for (int c = 0; c < 8; ++c) {
        if (c < 7) stage_chunk(sb, tid, c + 1, (c + 1) & 1, W0h, W0l, 256);
        CP_COMMIT();
        CP_WAIT(1);
        __syncthreads();
        const uint32_t bbase = sb + SM_B + (uint32_t)(c & 1) * BBUF;
        #pragma unroll
        for (int ks = 0; ks < 2; ++ks) {
            const int kA = c * 32 + ks * 16;
            uint32_t ah[2][4], al[2][4];
            #pragma unroll
            for (int mt = 0; mt < 2; ++mt) {
                uint32_t aaddr = sb + SM_AHI +
                    (uint32_t)((wr * 32 + mt * 16 + lrow) * AROW + (kA + lcol) * 2);
                ldsm_x4(ah[mt][0], ah[mt][1], ah[mt][2], ah[mt][3], aaddr);
                ldsm_x4(al[mt][0], al[mt][1], al[mt][2], al[mt][3],
                        aaddr + (SM_ALO - SM_AHI));
            }
            #pragma unroll
            for (int np = 0; np < 4; ++np) {
                uint32_t baddr = bbase +
                    (uint32_t)((wc * 64 + np * 16 + lrow) * BROW + (ks * 16 + lcol) * 2);
                uint32_t bh0, bh1, bh2, bh3, bl0, bl1, bl2, bl3;
                ldsm_x4(bh0, bh1, bh2, bh3, baddr);
                ldsm_x4(bl0, bl1, bl2, bl3, baddr + BHALF);
                #pragma unroll
                for (int mt = 0; mt < 2; ++mt) {
                    mma_bf16(acc[mt][2 * np],     ah[mt], bh0, bh2);
                    mma_bf16(acc[mt][2 * np + 1], ah[mt], bh1, bh3);
                    mma_bf16(acc[mt][2 * np],     al[mt], bh0, bh2);
                    mma_bf16(acc[mt][2 * np + 1], al[mt], bh1, bh3);
                    mma_bf16(acc[mt][2 * np],     ah[mt], bl0, bl2);
                    mma_bf16(acc[mt][2 * np + 1], ah[mt], bl1, bl3);
                }
            }
        }
        __syncthreads();
    }

    // prologue for GEMM2 chunk0 (hidden behind epilogue1)
    stage_chunk(sb, tid, 0, 0, W1h, W1l, 128);
    CP_COMMIT();

    // ---- epilogue1: bias+relu, hi/lo split, write H back into A tiles ------
    #pragma unroll
    for (int mt = 0; mt < 2; ++mt)
        #pragma unroll
        for (int nt = 0; nt < 8; ++nt) {
            int cc = wc * 64 + nt * 8 + 2 * (lane & 3);
            int r0 = wr * 32 + mt * 16 + (lane >> 2);
            float* d = acc[mt][nt];
            float v0 = fmaxf(d[0] + b0s[cc], 0.f), v1 = fmaxf(d[1] + b0s[cc + 1], 0.f);
            float v2 = fmaxf(d[2] + b0s[cc], 0.f), v3 = fmaxf(d[3] + b0s[cc + 1], 0.f);
            __nv_bfloat16 h0 = __float2bfloat16(v0), h1 = __float2bfloat16(v1);
            __nv_bfloat16 h2 = __float2bfloat16(v2), h3 = __float2bfloat16(v3);
            int o0 = r0 * AROW + cc * 2;
            int o1 = (r0 + 8) * AROW + cc * 2;
            *reinterpret_cast<uint32_t*>(smc + SM_AHI + o0) = pack_bf16(v0, v1);
            *reinterpret_cast<uint32_t*>(smc + SM_AHI + o1) = pack_bf16(v2, v3);
            *reinterpret_cast<uint32_t*>(smc + SM_ALO + o0) =
                pack_bf16(v0 - __bfloat162float(h0), v1 - __bfloat162float(h1));
            *reinterpret_cast<uint32_t*>(smc + SM_ALO + o1) =
                pack_bf16(v2 - __bfloat162float(h2), v3 - __bfloat162float(h3));
        }

    // ======================= GEMM2: M = relu(H@W1+b1) =======================
    // warp tile 32 x 32, acc2[2][4][4]
    float ac2[2][4][4];
    #pragma unroll
    for (int m = 0; m < 2; ++m)
        #pragma unroll
        for (int n = 0; n < 4; ++n)
            #pragma unroll
            for (int q = 0; q < 4; ++q) ac2[m][n][q] = 0.f;

    for (int c = 0; c < 8; ++c) {
        if (c < 7) stage_chunk(sb, tid, c + 1, (c + 1) & 1, W1h, W1l, 128);
        CP_COMMIT();
        CP_WAIT(1);
        __syncthreads();
        const uint32_t bbase = sb + SM_B + (uint32_t)(c & 1) * BBUF;
        #pragma unroll
        for (int ks = 0; ks < 2; ++ks) {
            const int kA = c * 32 + ks * 16;
            uint32_t ah[2][4], al[2][4];
            #pragma unroll
            for (int mt = 0; mt < 2; ++mt) {
                uint32_t aaddr = sb + SM_AHI +
                    (uint32_t)((wr * 32 + mt * 16 + lrow) * AROW + (kA + lcol) * 2);
                ldsm_x4(ah[mt][0], ah[mt][1], ah[mt][2], ah[mt][3], aaddr);
                ldsm_x4(al[mt][0], al[mt][1], al[mt][2], al[mt][3],
                        aaddr + (SM_ALO - SM_AHI));
            }
            #pragma unroll
            for (int np = 0; np < 2; ++np) {
                uint32_t baddr = bbase +
                    (uint32_t)((wc * 32 + np * 16 + lrow) * BROW + (ks * 16 + lcol) * 2);
                uint32_t bh0, bh1, bh2, bh3, bl0, bl1, bl2, bl3;
                ldsm_x4(bh0, bh1, bh2, bh3, baddr);
                ldsm_x4(bl0, bl1, bl2, bl3, baddr + BHALF);
                #pragma unroll
                for (int mt = 0; mt < 2; ++mt) {
                    mma_bf16(ac2[mt][2 * np],     ah[mt], bh0, bh2);
                    mma_bf16(ac2[mt][2 * np + 1], ah[mt], bh1, bh3);
                    mma_bf16(ac2[mt][2 * np],     al[mt], bh0, bh2);
                    mma_bf16(ac2[mt][2 * np + 1], al[mt], bh1, bh3);
                    mma_bf16(ac2[mt][2 * np],     ah[mt], bl0, bl2);
                    mma_bf16(ac2[mt][2 * np + 1], ah[mt], bl1, bl3);
                }
            }
        }
        __syncthreads();
    }

    // ---- epilogue2: bias+relu, scatter-atomic / residual store -------------
    #pragma unroll
    for (int mt = 0; mt < 2; ++mt)
        #pragma unroll
        for (int nt = 0; nt < 4; ++nt) {
            int cc = wc * 32 + nt * 8 + 2 * (lane & 3);
            int r0 = wr * 32 + mt * 16 + (lane >> 2);
            int r1 = r0 + 8;
            float* d = ac2[mt][nt];
            float v0 = fmaxf(d[0] + b1s[cc], 0.f), v1 = fmaxf(d[1] + b1s[cc + 1], 0.f);
            float v2 = fmaxf(d[2] + b1s[cc], 0.f), v3 = fmaxf(d[3] + b1s[cc + 1], 0.f);
            if (is_edge) {
                if (r0 < rem) {
                    float* a = g_agg + (size_t)sto[r0] * DD + cc;
                    atomicAdd(a, v0);
                    atomicAdd(a + 1, v1);
                }
                if (r1 < rem) {
                    float* a = g_agg + (size_t)sto[r1] * DD + cc;
                    atomicAdd(a, v2);
                    atomicAdd(a + 1, v3);
                }
            } else {
                int n0 = tile0 + r0, n1 = tile0 + r1;
                if (n0 < NN) {
                    float2 f = *reinterpret_cast<const float2*>(feat + (size_t)n0 * DD + cc);
                    *reinterpret_cast<float2*>(outp + (size_t)n0 * DD + cc) =
                        make_float2(f.x + v0, f.y + v1);
                }
                if (n1 < NN) {
                    float2 f = *reinterpret_cast<const float2*>(feat + (size_t)n1 * DD + cc);
                    *reinterpret_cast<float2*>(outp + (size_t)n1 * DD + cc) =
                        make_float2(f.x + v2, f.y + v3);
                }
            }
        }
}

// ============================== host launch =================================
extern "C" void kernel_launch(void* const* d_in, const int* in_sizes, int n_in,
                              void* d_out, int out_size)
{
    const float* feat  = (const float*)d_in[0];
    const int*   f_idx = (const int*)  d_in[1];
    const int*   t_idx = (const int*)  d_in[2];
    const float* msgW0 = (const float*)d_in[3];
    const float* msgb0 = (const float*)d_in[4];
    const float* msgW1 = (const float*)d_in[5];
    const float* msgb1 = (const float*)d_in[6];
    const float* updW0 = (const float*)d_in[7];
    const float* updb0 = (const float*)d_in[8];
    const float* updW1 = (const float*)d_in[9];
    const float* updb1 = (const float*)d_in[10];
    float* out = (float*)d_out;

    cudaFuncSetAttribute(mlp_kernel, cudaFuncAttributeMaxDynamicSharedMemorySize, SMEM_TOTAL);

    conv_w_kernel<<<768, 256>>>(msgW0, updW0, msgW1, updW1);
    zero_agg_kernel<<<1024, 256>>>();

    const int edge_tiles = (NE + TM - 1) / TM;  // 4688
    const int node_tiles = (NN + TM - 1) / TM;  // 391
    mlp_kernel<<<edge_tiles, 512, SMEM_TOTAL>>>(1, feat, f_idx, t_idx, msgb0, msgb1, nullptr);
    mlp_kernel<<<node_tiles, 512, SMEM_TOTAL>>>(0, feat, f_idx, t_idx, updb0, updb1, out);
}